// round 8
// baseline (speedup 1.0000x reference)
#include <cuda_runtime.h>
#include <math.h>

#define NSIG   (1 << 22)              // 4194304 = HOP * N_FRAMES
#define NFR    16384
#define NBIN   513
#define HOPSZ  256
#define OUTLEN ((NFR - 1) * HOPSZ)    // 4194048
#define LVOFF(l) ((1 << 22) - (1 << (23 - (l))))

// ------------------------- device scratch (static per rules) -------------------
__device__ float  g_f0[NFR];
__device__ float  g_f0up[NSIG];
__device__ float  g_lv[NSIG];                    // pair-sum levels 1..22 packed
__device__ float  g_pulse[NSIG];
__device__ float  g_envTn[(size_t)NFR * NBIN];   // transposed log-envelopes [t][k]
__device__ float  g_envTp[(size_t)NFR * NBIN];
__device__ float  g_frames[(size_t)NFR * 1024];  // windowed synthesis frames
__device__ float2 g_tw[256];                     // exp(-2*pi*i*t/1024), t<256
__device__ float  g_w[1024];                     // hann window
__device__ float  g_wsqinv[256];                 // 1/sum_{k} w^2(n0+256k), interior

// ------------------------------- init tables -----------------------------------
__global__ void k_init() {
  int tid = threadIdx.x;                          // <<<1,1024>>>
  if (tid < 256) {
    double ang = -2.0 * 3.14159265358979323846 * (double)tid / 1024.0;
    g_tw[tid] = make_float2((float)cos(ang), (float)sin(ang));
  }
  g_w[tid] = 0.5f * (1.0f - cosf((float)tid * (6.28318530717958647692f / 1024.0f)));
  __syncthreads();
  if (tid < 256) {
    // same accumulation order as the OLA loop (n descending)
    float w3 = g_w[tid + 768], w2 = g_w[tid + 512], w1 = g_w[tid + 256], w0 = g_w[tid];
    float a = w3 * w3;
    a += w2 * w2;
    a += w1 * w1;
    a += w0 * w0;
    g_wsqinv[tid] = 1.0f / fmaxf(a, 1e-11f);
  }
}

// --------------------- impulse train (bit-replicates JAX) ----------------------
__global__ void k_exp(const float* __restrict__ log_f0) {
  int i = blockIdx.x * blockDim.x + threadIdx.x;
  if (i < NFR) g_f0[i] = expf(log_f0[i]);
}

__global__ void k_interp() {
  int i = blockIdx.x * blockDim.x + threadIdx.x;
  float fi  = (float)i;
  float pos = __fsub_rn(__fdiv_rn(__fadd_rn(fi, 0.5f), 256.0f), 0.5f);
  pos = fminf(fmaxf(pos, 0.0f), 16383.0f);
  float flo = floorf(pos);
  int lo = (int)flo;
  int hi = lo + 1; if (hi > 16383) hi = 16383;
  float frac = __fsub_rn(pos, flo);
  float a = __fmul_rn(g_f0[lo], __fsub_rn(1.0f, frac));
  float b = __fmul_rn(g_f0[hi], frac);
  g_f0up[i] = __fadd_rn(a, b);
}

// pair-sum levels 1..10 (levels 1-2 in registers; identical __fadd_rn tree)
__global__ __launch_bounds__(256) void k_scan_lo() {
  __shared__ float s[256];
  int b = blockIdx.x, t = threadIdx.x;
  float4 x = ((const float4*)g_f0up)[b * 256 + t];
  float a0 = __fadd_rn(x.x, x.y);
  float a1 = __fadd_rn(x.z, x.w);
  float c  = __fadd_rn(a0, a1);
  ((float2*)(g_lv + LVOFF(1)))[b * 256 + t] = make_float2(a0, a1);
  g_lv[LVOFF(2) + b * 256 + t] = c;
  s[t] = c;
  __syncthreads();
  int n = 128;
  #pragma unroll
  for (int l = 3; l <= 10; l++) {
    float v = 0.0f;
    if (t < n) v = __fadd_rn(s[2 * t], s[2 * t + 1]);
    __syncthreads();
    if (t < n) { s[t] = v; g_lv[LVOFF(l) + b * n + t] = v; }
    __syncthreads();
    n >>= 1;
  }
}

// pair-sum levels 11..22, single block
__global__ __launch_bounds__(1024) void k_scan_hi() {
  __shared__ float s[4096];
  int t = threadIdx.x;
  #pragma unroll
  for (int q = 0; q < 4; q++) s[t + q * 1024] = g_lv[LVOFF(10) + t + q * 1024];
  __syncthreads();
  int n = 2048;
  for (int l = 11; l <= 22; l++) {
    float v0 = 0.0f, v1 = 0.0f;
    if (t < n)        v0 = __fadd_rn(s[2 * t], s[2 * t + 1]);
    if (t + 1024 < n) v1 = __fadd_rn(s[2 * (t + 1024)], s[2 * (t + 1024) + 1]);
    __syncthreads();
    if (t < n)        { s[t] = v0;        g_lv[LVOFF(l) + t] = v0; }
    if (t + 1024 < n) { s[t + 1024] = v1; g_lv[LVOFF(l) + t + 1024] = v1; }
    __syncthreads();
    n >>= 1;
  }
}

// cumsum closed form (jax associative_scan): left-fold of dyadic blocks of [0..n]
__device__ __forceinline__ float saw_at(int n) {
  int m = n + 1;
  float acc = 0.0f;
  bool first = true;
  int start = 0;
  #pragma unroll
  for (int l = 22; l >= 0; --l) {
    if (m & (1 << l)) {
      float v = (l == 0) ? g_f0up[start]
                         : g_lv[LVOFF(l) + (start >> l)];
      acc = first ? v : __fadd_rn(acc, v);
      first = false;
      start += (1 << l);
    }
  }
  float phase = __fdiv_rn(acc, 24000.0f);
  return __fsub_rn(phase, floorf(phase));
}

__global__ __launch_bounds__(256) void k_sawimp() {
  __shared__ float ssaw[257];
  int base = blockIdx.x * 256;
  int t = threadIdx.x;
  ssaw[t] = saw_at(base + t);
  if (t == 0) ssaw[256] = saw_at((base + 256) & (NSIG - 1));
  __syncthreads();
  float d = __fdiv_rn(g_f0up[base + t], 24000.0f);
  g_pulse[base + t] = __fadd_rn(__fsub_rn(ssaw[t], ssaw[t + 1]), d);
}

// --------- fused envelope transposes [513][16384] -> [16384][513] (both) --------
__global__ void k_transpose2(const float* __restrict__ in_n,
                             const float* __restrict__ in_p) {
  __shared__ float tile[32][33];
  int t0 = blockIdx.x * 32, k0 = blockIdx.y * 32;
  int x = t0 + threadIdx.x, y = k0 + threadIdx.y;
  int tx = t0 + threadIdx.y, kx = k0 + threadIdx.x;

  if (y < NBIN) tile[threadIdx.y][threadIdx.x] = in_n[(size_t)y * NFR + x];
  __syncthreads();
  if (kx < NBIN) g_envTn[(size_t)tx * NBIN + kx] = tile[threadIdx.x][threadIdx.y];
  __syncthreads();
  if (y < NBIN) tile[threadIdx.y][threadIdx.x] = in_p[(size_t)y * NFR + x];
  __syncthreads();
  if (kx < NBIN) g_envTp[(size_t)tx * NBIN + kx] = tile[threadIdx.x][threadIdx.y];
}

// ----------------- FMA-pipe transcendentals (no MUFU) ---------------------------
__device__ __forceinline__ float fexp(float x) {
  float y = x * 1.4426950408889634f;
  float n = rintf(y);
  float f = y - n;                            // [-0.5, 0.5]
  float p = 1.5403530e-4f;                    // ln2^6/720
  p = fmaf(p, f, 1.3333558e-3f);              // ln2^5/120
  p = fmaf(p, f, 9.6181291e-3f);              // ln2^4/24
  p = fmaf(p, f, 5.5504109e-2f);              // ln2^3/6
  p = fmaf(p, f, 2.4022651e-1f);              // ln2^2/2
  p = fmaf(p, f, 6.9314718e-1f);              // ln2
  p = fmaf(p, f, 1.0f);
  n = fminf(fmaxf(n, -126.0f), 126.0f);
  float s = __int_as_float(((int)n + 127) << 23);
  return p * s;
}

__device__ __forceinline__ float2 fsincos(float x) {   // (sin x, cos x)
  float t = x * 0.15915494309189535f;         // x/(2π)
  float r = t - rintf(t);                     // [-0.5, 0.5]
  float ph = r * 3.14159265358979f;           // φ = πr ∈ [-π/2, π/2], θ = 2φ
  float z = ph * ph;
  float sp = 2.7557319e-6f;                   // 1/362880
  sp = fmaf(sp, z, -1.9841270e-4f);           // -1/5040
  sp = fmaf(sp, z, 8.3333333e-3f);            // 1/120
  sp = fmaf(sp, z, -1.6666667e-1f);           // -1/6
  sp = fmaf(sp * z, ph, ph);                  // sin φ
  float cp = -2.7557319e-7f;                  // -1/3628800
  cp = fmaf(cp, z, 2.4801587e-5f);            // 1/40320
  cp = fmaf(cp, z, -1.3888889e-3f);           // -1/720
  cp = fmaf(cp, z, 4.1666667e-2f);            // 1/24
  cp = fmaf(cp, z, -0.5f);
  cp = fmaf(cp, z, 1.0f);                     // cos φ
  float s2 = 2.0f * sp;
  return make_float2(s2 * cp, fmaf(-s2, sp, 1.0f));
}

// ------------------------ register FFT building blocks -------------------------
__device__ __forceinline__ float2 cmul(float2 a, float2 b) {
  return make_float2(a.x * b.x - a.y * b.y, a.x * b.y + a.y * b.x);
}

__device__ __forceinline__ void dft4(float2& x0, float2& x1, float2& x2, float2& x3,
                                     float sgn) {
  float t0x = x0.x + x2.x, t0y = x0.y + x2.y;
  float t1x = x0.x - x2.x, t1y = x0.y - x2.y;
  float t2x = x1.x + x3.x, t2y = x1.y + x3.y;
  float t3x = x1.x - x3.x, t3y = x1.y - x3.y;
  x0 = make_float2(t0x + t2x, t0y + t2y);
  x2 = make_float2(t0x - t2x, t0y - t2y);
  x1 = make_float2(t1x + sgn * t3y, t1y - sgn * t3x);
  x3 = make_float2(t1x - sgn * t3y, t1y + sgn * t3x);
}

__device__ __forceinline__ void dft8(float2 c[8], float sgn) {
  const float R2 = 0.70710678118654752f;
  float2 e0 = c[0], e1 = c[2], e2 = c[4], e3 = c[6];
  float2 o0 = c[1], o1 = c[3], o2 = c[5], o3 = c[7];
  dft4(e0, e1, e2, e3, sgn);
  dft4(o0, o1, o2, o3, sgn);
  float2 T1 = make_float2(R2 * (o1.x + sgn * o1.y), R2 * (o1.y - sgn * o1.x));
  float2 T2 = make_float2(sgn * o2.y, -sgn * o2.x);
  float2 T3 = make_float2(R2 * (sgn * o3.y - o3.x), R2 * (-sgn * o3.x - o3.y));
  c[0] = make_float2(e0.x + o0.x, e0.y + o0.y);
  c[4] = make_float2(e0.x - o0.x, e0.y - o0.y);
  c[1] = make_float2(e1.x + T1.x, e1.y + T1.y);
  c[5] = make_float2(e1.x - T1.x, e1.y - T1.y);
  c[2] = make_float2(e2.x + T2.x, e2.y + T2.y);
  c[6] = make_float2(e2.x - T2.x, e2.y - T2.y);
  c[3] = make_float2(e3.x + T3.x, e3.y + T3.y);
  c[7] = make_float2(e3.x - T3.x, e3.y - T3.y);
}

__device__ __forceinline__ void dft16(float2 c[16], float sgn) {
  const float C1 = 0.92387953251128676f;
  const float S1 = 0.38268343236508977f;
  const float R2 = 0.70710678118654752f;
  float2 e[8], o[8];
  #pragma unroll
  for (int q = 0; q < 8; q++) { e[q] = c[2 * q]; o[q] = c[2 * q + 1]; }
  dft8(e, sgn);
  dft8(o, sgn);
  float2 w[8];
  w[0] = make_float2(1.0f, 0.0f);
  w[1] = make_float2(C1, -sgn * S1);
  w[2] = make_float2(R2, -sgn * R2);
  w[3] = make_float2(S1, -sgn * C1);
  w[4] = make_float2(0.0f, -sgn);
  w[5] = make_float2(-S1, -sgn * C1);
  w[6] = make_float2(-R2, -sgn * R2);
  w[7] = make_float2(-C1, -sgn * S1);
  #pragma unroll
  for (int r = 0; r < 8; r++) {
    float2 T = cmul(o[r], w[r]);
    c[r]     = make_float2(e[r].x + T.x, e[r].y + T.y);
    c[r + 8] = make_float2(e[r].x - T.x, e[r].y - T.y);
  }
}

__device__ __forceinline__ int SW(int i) { return i + (i >> 4); }
#define WSN 1088

// 1024-pt FFT, 128 threads per group. Input in A (caller synced), output in B.
__device__ void fftg(float2* A, float2* B, int t, bool inv) {
  const float sgn = inv ? -1.0f : 1.0f;
  { // stage 1: radix-8, m=1, j=t
    float2 c[8];
    #pragma unroll
    for (int q = 0; q < 8; q++) c[q] = A[SW(t + 128 * q)];
    dft8(c, sgn);
    float2 w0 = __ldg(&g_tw[t]);
    float2 wc = make_float2(w0.x, sgn * w0.y);
    float2 u = wc;
    c[1] = cmul(c[1], u);
    #pragma unroll
    for (int r = 2; r < 8; r++) { u = cmul(u, wc); c[r] = cmul(c[r], u); }
    #pragma unroll
    for (int r = 0; r < 8; r++) B[SW(8 * t + r)] = c[r];
  }
  __syncthreads();
  { // stage 2: radix-8, m=8
    float2 c[8];
    #pragma unroll
    for (int q = 0; q < 8; q++) c[q] = B[SW(t + 128 * q)];
    dft8(c, sgn);
    int j = t >> 3, k = t & 7;
    float2 w0 = __ldg(&g_tw[8 * j]);
    float2 wc = make_float2(w0.x, sgn * w0.y);
    float2 u = wc;
    c[1] = cmul(c[1], u);
    #pragma unroll
    for (int r = 2; r < 8; r++) { u = cmul(u, wc); c[r] = cmul(c[r], u); }
    int o = k + 64 * j;
    #pragma unroll
    for (int r = 0; r < 8; r++) A[SW(o + 8 * r)] = c[r];
  }
  __syncthreads();
  if (t < 64) { // stage 3: radix-16, m=64, j=0 -> no twiddles
    float2 c[16];
    #pragma unroll
    for (int q = 0; q < 16; q++) c[q] = A[SW(t + 64 * q)];
    dft16(c, sgn);
    #pragma unroll
    for (int r = 0; r < 16; r++) B[SW(t + 64 * r)] = c[r];
  }
  __syncthreads();
}

// ------------------------------ per-4-frame mega-kernel -------------------------
__global__ __launch_bounds__(256) void k_frames(const float* __restrict__ noise) {
  __shared__ __align__(16) float2 ws[2][2][WSN];

  int tid = threadIdx.x;
  int g  = tid >> 7;
  int tt = tid & 127;
  int f0 = 4 * blockIdx.x + 2 * g;
  int f1 = f0 + 1;
  float2* WA = ws[g][0];
  float2* WB = ws[g][1];

  // ---- phase 1: packed min-phase input (log-env of f0 + i*f1, symmetric) ----
  #pragma unroll
  for (int q = 0; q < 8; q++) {
    int n = tt + 128 * q;
    int k = (n <= 512) ? n : 1024 - n;
    WA[SW(n)] = make_float2(g_envTp[(size_t)f0 * NBIN + k],
                            g_envTp[(size_t)f1 * NBIN + k]);
  }
  __syncthreads();
  fftg(WA, WB, tt, true);          // cep0*1024 in Re, cep1*1024 in Im

  // ---- phase 2: fold ----
  #pragma unroll
  for (int q = 0; q < 8; q++) {
    int n = tt + 128 * q;
    float f = (n == 0 || n == 512) ? 1.0f : (n < 512 ? 2.0f : 0.0f);
    float sc = f * (1.0f / 1024.0f);
    float2 v = WB[SW(n)];
    WA[SW(n)] = make_float2(v.x * sc, v.y * sc);
  }
  __syncthreads();
  fftg(WA, WB, tt, false);         // packed C spectra

  // ---- phase 3: min-phase exp -> registers ----
  float2 MP0[5], MP1[5];
  #pragma unroll
  for (int q = 0; q < 5; q++) {
    int k = tt + 128 * q;
    if (k <= 512) {
      float2 z  = WB[SW(k)];
      float2 zm = WB[SW((1024 - k) & 1023)];
      float2 C0 = make_float2(0.5f * (z.x + zm.x),  0.5f * (z.y - zm.y));
      float2 C1 = make_float2(0.5f * (z.y + zm.y), -0.5f * (z.x - zm.x));
      float m0 = fexp(C0.x);
      float2 sc0 = fsincos(C0.y);
      MP0[q] = make_float2(m0 * sc0.y, m0 * sc0.x);
      float m1 = fexp(C1.x);
      float2 sc1 = fsincos(C1.y);
      MP1[q] = make_float2(m1 * sc1.y, m1 * sc1.x);
    }
  }

  // ---- phase 4: analysis FFT frame f0 (noise + i*pulse) ----
  #pragma unroll
  for (int q = 0; q < 8; q++) {
    int n = tt + 128 * q;
    int gi = f0 * 256 - 256 + n;
    if (gi < 0) gi = -gi;
    else if (gi >= NSIG) gi = 2 * NSIG - 2 - gi;
    float w = g_w[n];
    WA[SW(n)] = make_float2(noise[gi] * w, g_pulse[gi] * w);
  }
  __syncthreads();
  fftg(WA, WB, tt, false);

  float2 S0[5];
  #pragma unroll
  for (int q = 0; q < 5; q++) {
    int k = tt + 128 * q;
    if (k <= 512) {
      float2 z1 = WB[SW(k)];
      float2 z2 = WB[SW((1024 - k) & 1023)];
      float en = fexp(g_envTn[(size_t)f0 * NBIN + k]);
      float2 N = make_float2(0.5f * (z1.x + z2.x) * en, 0.5f * (z1.y - z2.y) * en);
      float2 P = make_float2(0.5f * (z1.y + z2.y),      0.5f * (z2.x - z1.x));
      float2 PM = cmul(P, MP0[q]);
      S0[q] = make_float2(N.x + PM.x, N.y + PM.y);
    }
  }

  // ---- phase 5: analysis FFT frame f1, combine, packed synth spectrum ----
  #pragma unroll
  for (int q = 0; q < 8; q++) {
    int n = tt + 128 * q;
    int gi = f1 * 256 - 256 + n;
    if (gi < 0) gi = -gi;
    else if (gi >= NSIG) gi = 2 * NSIG - 2 - gi;
    float w = g_w[n];
    WA[SW(n)] = make_float2(noise[gi] * w, g_pulse[gi] * w);
  }
  __syncthreads();
  fftg(WA, WB, tt, false);

  #pragma unroll
  for (int q = 0; q < 5; q++) {
    int k = tt + 128 * q;
    if (k <= 512) {
      float2 z1 = WB[SW(k)];
      float2 z2 = WB[SW((1024 - k) & 1023)];
      float en = fexp(g_envTn[(size_t)f1 * NBIN + k]);
      float2 N = make_float2(0.5f * (z1.x + z2.x) * en, 0.5f * (z1.y - z2.y) * en);
      float2 P = make_float2(0.5f * (z1.y + z2.y),      0.5f * (z2.x - z1.x));
      float2 PM = cmul(P, MP1[q]);
      float2 s1 = make_float2(N.x + PM.x, N.y + PM.y);
      float2 s0 = S0[q];
      if (k == 0 || k == 512) { s0.y = 0.0f; s1.y = 0.0f; }   // irfft drops these
      WA[SW(k)] = make_float2(s0.x - s1.y, s0.y + s1.x);
      if (k > 0 && k < 512)
        WA[SW(1024 - k)] = make_float2(s0.x + s1.y, s1.x - s0.y);
    }
  }
  __syncthreads();

  // ---- phase 6: packed synthesis iFFT, window, store both frames ----
  fftg(WA, WB, tt, true);

  #pragma unroll
  for (int q = 0; q < 8; q++) {
    int n = tt + 128 * q;
    float wsc = (1.0f / 1024.0f) * g_w[n];
    float2 v = WB[SW(n)];
    g_frames[(size_t)f0 * 1024 + n] = v.x * wsc;
    g_frames[(size_t)f1 * 1024 + n] = v.y * wsc;
  }
}

// ----------------------------- overlap-add + wsq -------------------------------
__global__ void k_ola(float* __restrict__ out) {
  int i = blockIdx.x * blockDim.x + threadIdx.x;
  if (i >= OUTLEN) return;
  int p = i + 512;
  if (i >= 256 && i < OUTLEN - 256) {          // interior: exactly 4 full frames
    int jhi = p >> 8;
    int n0 = p & 255;
    const float* base = g_frames + (size_t)(jhi - 3) * 1024;
    float acc = base[n0 + 768];
    acc += base[1024 + n0 + 512];
    acc += base[2048 + n0 + 256];
    acc += base[3072 + n0];
    out[i] = acc * g_wsqinv[n0];
  } else {
    int jhi = p >> 8;
    int jlo = jhi - 3;
    if (jlo < 0) jlo = 0;
    if (jhi > NFR - 1) jhi = NFR - 1;
    float acc = 0.0f, wsq = 0.0f;
    for (int j = jlo; j <= jhi; j++) {
      int n = p - (j << 8);
      acc += g_frames[(size_t)j * 1024 + n];
      float w = g_w[n];
      wsq += w * w;
    }
    out[i] = acc / fmaxf(wsq, 1e-11f);
  }
}

// --------------------------------- launcher ------------------------------------
extern "C" void kernel_launch(void* const* d_in, const int* in_sizes, int n_in,
                              void* d_out, int out_size) {
  const float* log_f0  = (const float*)d_in[0];
  const float* env_noi = (const float*)d_in[1];
  const float* env_per = (const float*)d_in[2];
  const float* noise   = (const float*)d_in[3];
  float* out = (float*)d_out;

  k_init<<<1, 1024>>>();
  k_exp<<<NFR / 256, 256>>>(log_f0);
  k_interp<<<NSIG / 256, 256>>>();
  k_scan_lo<<<NSIG / 1024, 256>>>();
  k_scan_hi<<<1, 1024>>>();
  k_sawimp<<<NSIG / 256, 256>>>();
  dim3 tb(32, 32);
  dim3 tg(NFR / 32, (NBIN + 31) / 32);
  k_transpose2<<<tg, tb>>>(env_noi, env_per);
  k_frames<<<NFR / 4, 256>>>(noise);
  k_ola<<<(OUTLEN + 255) / 256, 256>>>(out);
}